// round 1
// baseline (speedup 1.0000x reference)
#include <cuda_runtime.h>
#include <cuda_bf16.h>

// Problem constants
#define B_SZ 8192
#define K_SZ 32
#define D_SZ 512

// Scratch (device globals — no allocation allowed)
__device__ float4 g_q2[B_SZ * (D_SZ / 4)];   // 16 MB: q2 = x@M + c
__device__ float  g_M[D_SZ * D_SZ];          // 1 MB:  M = w1^T @ w2
__device__ float  g_c[D_SZ];                 // c = b1 @ w2

// ---------------------------------------------------------------------------
// Kernel 1: M[d,j] = sum_e w1[e,d] * w2[e,j]   (512x512x512, tiled 64x64x16)
// ---------------------------------------------------------------------------
__global__ void compute_M_kernel(const float* __restrict__ w1,
                                 const float* __restrict__ w2) {
    __shared__ float As[16][64];  // [e][d]
    __shared__ float Bs[16][64];  // [e][j]
    const int tid = threadIdx.x;           // 256 threads
    const int lRow = tid / 16;             // 0..15
    const int lCol = (tid % 16) * 4;       // 0..60
    const int d0 = blockIdx.y * 64;
    const int j0 = blockIdx.x * 64;
    const int tRow = (tid / 16) * 4;
    const int tCol = (tid % 16) * 4;

    float acc[4][4] = {};
    for (int e0 = 0; e0 < D_SZ; e0 += 16) {
        *(float4*)&As[lRow][lCol] = *(const float4*)(w1 + (e0 + lRow) * D_SZ + d0 + lCol);
        *(float4*)&Bs[lRow][lCol] = *(const float4*)(w2 + (e0 + lRow) * D_SZ + j0 + lCol);
        __syncthreads();
#pragma unroll
        for (int e = 0; e < 16; e++) {
            float rm[4], rn[4];
#pragma unroll
            for (int i = 0; i < 4; i++) rm[i] = As[e][tRow + i];
#pragma unroll
            for (int j = 0; j < 4; j++) rn[j] = Bs[e][tCol + j];
#pragma unroll
            for (int i = 0; i < 4; i++)
#pragma unroll
                for (int j = 0; j < 4; j++)
                    acc[i][j] = fmaf(rm[i], rn[j], acc[i][j]);
        }
        __syncthreads();
    }
#pragma unroll
    for (int i = 0; i < 4; i++) {
        float4 v = make_float4(acc[i][0], acc[i][1], acc[i][2], acc[i][3]);
        *(float4*)(g_M + (d0 + tRow + i) * D_SZ + j0 + tCol) = v;
    }
}

// ---------------------------------------------------------------------------
// Kernel 2: c[j] = sum_e b1[e] * w2[e,j]
// ---------------------------------------------------------------------------
__global__ void compute_c_kernel(const float* __restrict__ b1,
                                 const float* __restrict__ w2) {
    const int j = blockIdx.x * 128 + threadIdx.x;  // grid 4 x 128
    float s = 0.f;
    for (int e = 0; e < D_SZ; e++)
        s = fmaf(b1[e], w2[e * D_SZ + j], s);
    g_c[j] = s;
}

// ---------------------------------------------------------------------------
// Kernel 3: q2 = x @ M + c     (8192x512x512, tiled 128x128x8, 8x8/thread)
// ---------------------------------------------------------------------------
__global__ void __launch_bounds__(256)
gemm_q2_kernel(const float* __restrict__ X) {
    __shared__ float As[8][128];   // transposed A tile [k][m]
    __shared__ float Bs[8][128];   // B tile [k][n]
    const int tid = threadIdx.x;
    const int bm = blockIdx.y;     // 0..63
    const int bn = blockIdx.x;     // 0..3

    const int aRow = tid / 2;            // 0..127
    const int aCol = (tid % 2) * 4;      // 0 or 4
    const int bRow = tid / 32;           // 0..7
    const int bCol = (tid % 32) * 4;     // 0..124
    const int tRow = (tid / 16) * 8;
    const int tCol = (tid % 16) * 8;

    const float* Aptr = X + (long)(bm * 128) * D_SZ;
    const float* Bptr = g_M + bn * 128;

    float acc[8][8] = {};
    for (int k0 = 0; k0 < D_SZ; k0 += 8) {
        float4 av = *(const float4*)(Aptr + aRow * D_SZ + k0 + aCol);
        As[aCol + 0][aRow] = av.x;
        As[aCol + 1][aRow] = av.y;
        As[aCol + 2][aRow] = av.z;
        As[aCol + 3][aRow] = av.w;
        *(float4*)&Bs[bRow][bCol] = *(const float4*)(Bptr + (k0 + bRow) * D_SZ + bCol);
        __syncthreads();
#pragma unroll
        for (int kk = 0; kk < 8; kk++) {
            float rm[8], rn[8];
#pragma unroll
            for (int i = 0; i < 8; i++) rm[i] = As[kk][tRow + i];
#pragma unroll
            for (int j = 0; j < 8; j++) rn[j] = Bs[kk][tCol + j];
#pragma unroll
            for (int i = 0; i < 8; i++)
#pragma unroll
                for (int j = 0; j < 8; j++)
                    acc[i][j] = fmaf(rm[i], rn[j], acc[i][j]);
        }
        __syncthreads();
    }

    float creg[8];
#pragma unroll
    for (int j = 0; j < 8; j++) creg[j] = g_c[bn * 128 + tCol + j];

    float* Cptr = (float*)g_q2 + (long)(bm * 128 + tRow) * D_SZ + bn * 128 + tCol;
#pragma unroll
    for (int i = 0; i < 8; i++) {
#pragma unroll
        for (int j = 0; j < 8; j += 4) {
            float4 v = make_float4(acc[i][j + 0] + creg[j + 0],
                                   acc[i][j + 1] + creg[j + 1],
                                   acc[i][j + 2] + creg[j + 2],
                                   acc[i][j + 3] + creg[j + 3]);
            *(float4*)(Cptr + (long)i * D_SZ + j) = v;
        }
    }
}

// ---------------------------------------------------------------------------
// Kernel 4: attention. One CTA per b (256 threads):
//   scores[k] = (q2[b]·keys[b,k]) / sqrt(D); softmax over k;
//   out = 0.5*x + 0.5*sum_k attn[k]*values[b,k]
// ---------------------------------------------------------------------------
__global__ void __launch_bounds__(256)
attn_kernel(const float* __restrict__ x,
            const float* __restrict__ keys,
            const float* __restrict__ values,
            float* __restrict__ out) {
    const int b = blockIdx.x;
    const int tid = threadIdx.x;
    const int lane = tid & 31;
    const int warp = tid >> 5;

    __shared__ float4 q2s[128];
    __shared__ float sc[32];
    __shared__ float attn_s[32];

    if (tid < 128) q2s[tid] = g_q2[b * 128 + tid];
    __syncthreads();

    // scores: 8 warps x 4 k each, float4 loads
    const float4* K4 = (const float4*)keys;
#pragma unroll
    for (int kk = 0; kk < 4; kk++) {
        const int k = warp * 4 + kk;
        const long base = ((long)b * K_SZ + k) * 128;
        float s = 0.f;
#pragma unroll
        for (int i = 0; i < 4; i++) {
            float4 kv = K4[base + i * 32 + lane];
            float4 qv = q2s[i * 32 + lane];
            s = fmaf(kv.x, qv.x, s);
            s = fmaf(kv.y, qv.y, s);
            s = fmaf(kv.z, qv.z, s);
            s = fmaf(kv.w, qv.w, s);
        }
#pragma unroll
        for (int off = 16; off; off >>= 1)
            s += __shfl_xor_sync(0xffffffffu, s, off);
        if (lane == 0) sc[k] = s * 0.044194173824159216f;  // 1/sqrt(512)
    }
    __syncthreads();

    // softmax over 32 scores (one warp)
    if (tid < 32) {
        float s = sc[tid];
        float m = s;
#pragma unroll
        for (int off = 16; off; off >>= 1)
            m = fmaxf(m, __shfl_xor_sync(0xffffffffu, m, off));
        float p = __expf(s - m);
        float sum = p;
#pragma unroll
        for (int off = 16; off; off >>= 1)
            sum += __shfl_xor_sync(0xffffffffu, sum, off);
        attn_s[tid] = p / sum;
    }
    __syncthreads();

    // combined + blend, float2 per thread (256 threads x 2 = 512 dims)
    const float2* V2 = (const float2*)values;
    const float2* X2 = (const float2*)x;
    float2 acc = make_float2(0.f, 0.f);
    const long vbase = (long)b * K_SZ * 256;
#pragma unroll
    for (int k = 0; k < K_SZ; k++) {
        const float a = attn_s[k];
        float2 v = V2[vbase + k * 256 + tid];
        acc.x = fmaf(a, v.x, acc.x);
        acc.y = fmaf(a, v.y, acc.y);
    }
    float2 xv = X2[(long)b * 256 + tid];
    float2 o;
    o.x = 0.5f * xv.x + 0.5f * acc.x;
    o.y = 0.5f * xv.y + 0.5f * acc.y;
    ((float2*)out)[(long)b * 256 + tid] = o;
}

// ---------------------------------------------------------------------------
extern "C" void kernel_launch(void* const* d_in, const int* in_sizes, int n_in,
                              void* d_out, int out_size) {
    (void)in_sizes; (void)n_in; (void)out_size;
    const float* x      = (const float*)d_in[0];
    const float* keys   = (const float*)d_in[1];
    const float* values = (const float*)d_in[2];
    const float* w1     = (const float*)d_in[3];
    const float* b1     = (const float*)d_in[4];
    const float* w2     = (const float*)d_in[5];
    // d_in[6] = b2: contributes a per-row constant to scores -> cancels in softmax.
    float* out = (float*)d_out;

    compute_M_kernel<<<dim3(8, 8), 256>>>(w1, w2);
    compute_c_kernel<<<4, 128>>>(b1, w2);
    gemm_q2_kernel<<<dim3(4, 64), 256>>>(x);
    attn_kernel<<<B_SZ, 256>>>(x, keys, values, out);
}

// round 4
// speedup vs baseline: 1.1797x; 1.1797x over previous
#include <cuda_runtime.h>
#include <cuda_bf16.h>
#include <cstdint>

// Problem constants
#define B_SZ 8192
#define K_SZ 32
#define D_SZ 512
#define KC   1536            // concatenated K = 3*512 (xh|xl|xh vs Mh;Mh;Ml)
#define ASTRIDE 40           // smem row stride in bf16 halves (conflict-free ldmatrix)

// Scratch (device globals — no allocation allowed)
__device__ float4 g_q2[B_SZ * (D_SZ / 4)];            // 16 MB: q2 = x@M + c
__device__ float  g_M[D_SZ * D_SZ];                   // 1 MB:  M = w1^T @ w2
__device__ float  g_c[D_SZ];                          // c = b1 @ w2
__device__ __nv_bfloat16 g_A[B_SZ * KC];              // 25 MB: [xh | xl | xh]
__device__ __nv_bfloat16 g_Bop[D_SZ * KC];            // 1.5 MB: Bop[n][k] (K-major)

__device__ __forceinline__ uint32_t smem_u32(const void* p) {
    uint32_t a;
    asm("{ .reg .u64 t; cvta.to.shared.u64 t, %1; cvt.u32.u64 %0, t; }" : "=r"(a) : "l"(p));
    return a;
}

// ---------------------------------------------------------------------------
// Kernel 1: M[d,j] = sum_e w1[e,d] * w2[e,j]
// ---------------------------------------------------------------------------
__global__ void compute_M_kernel(const float* __restrict__ w1,
                                 const float* __restrict__ w2) {
    __shared__ float As[16][64];
    __shared__ float Bs[16][64];
    const int tid = threadIdx.x;
    const int lRow = tid / 16;
    const int lCol = (tid % 16) * 4;
    const int d0 = blockIdx.y * 64;
    const int j0 = blockIdx.x * 64;
    const int tRow = (tid / 16) * 4;
    const int tCol = (tid % 16) * 4;

    float acc[4][4] = {};
    for (int e0 = 0; e0 < D_SZ; e0 += 16) {
        *(float4*)&As[lRow][lCol] = *(const float4*)(w1 + (e0 + lRow) * D_SZ + d0 + lCol);
        *(float4*)&Bs[lRow][lCol] = *(const float4*)(w2 + (e0 + lRow) * D_SZ + j0 + lCol);
        __syncthreads();
#pragma unroll
        for (int e = 0; e < 16; e++) {
            float rm[4], rn[4];
#pragma unroll
            for (int i = 0; i < 4; i++) rm[i] = As[e][tRow + i];
#pragma unroll
            for (int j = 0; j < 4; j++) rn[j] = Bs[e][tCol + j];
#pragma unroll
            for (int i = 0; i < 4; i++)
#pragma unroll
                for (int j = 0; j < 4; j++)
                    acc[i][j] = fmaf(rm[i], rn[j], acc[i][j]);
        }
        __syncthreads();
    }
#pragma unroll
    for (int i = 0; i < 4; i++) {
        float4 v = make_float4(acc[i][0], acc[i][1], acc[i][2], acc[i][3]);
        *(float4*)(g_M + (d0 + tRow + i) * D_SZ + j0 + tCol) = v;
    }
}

// ---------------------------------------------------------------------------
// Kernel 2: c[j] = sum_e b1[e] * w2[e,j]
// ---------------------------------------------------------------------------
__global__ void compute_c_kernel(const float* __restrict__ b1,
                                 const float* __restrict__ w2) {
    const int j = blockIdx.x * 128 + threadIdx.x;
    float s = 0.f;
    for (int e = 0; e < D_SZ; e++)
        s = fmaf(b1[e], w2[e * D_SZ + j], s);
    g_c[j] = s;
}

// ---------------------------------------------------------------------------
// Kernel 3a: split x -> A' = [xh | xl | xh]  (bf16, [B, 1536])
// ---------------------------------------------------------------------------
__global__ void split_x_kernel(const float* __restrict__ x) {
    const int t = blockIdx.x * blockDim.x + threadIdx.x;  // 1,048,576 threads
    const int b = t >> 7;
    const int c4 = (t & 127) * 4;
    float4 v = *(const float4*)(x + (size_t)b * D_SZ + c4);
    __nv_bfloat16 hx = __float2bfloat16_rn(v.x), hy = __float2bfloat16_rn(v.y);
    __nv_bfloat16 hz = __float2bfloat16_rn(v.z), hw = __float2bfloat16_rn(v.w);
    __nv_bfloat16 lx = __float2bfloat16_rn(v.x - __bfloat162float(hx));
    __nv_bfloat16 ly = __float2bfloat16_rn(v.y - __bfloat162float(hy));
    __nv_bfloat16 lz = __float2bfloat16_rn(v.z - __bfloat162float(hz));
    __nv_bfloat16 lw = __float2bfloat16_rn(v.w - __bfloat162float(hw));
    __nv_bfloat16* row = g_A + (size_t)b * KC;
    uint2 hi, lo;
    ((__nv_bfloat16*)&hi)[0] = hx; ((__nv_bfloat16*)&hi)[1] = hy;
    ((__nv_bfloat16*)&hi)[2] = hz; ((__nv_bfloat16*)&hi)[3] = hw;
    ((__nv_bfloat16*)&lo)[0] = lx; ((__nv_bfloat16*)&lo)[1] = ly;
    ((__nv_bfloat16*)&lo)[2] = lz; ((__nv_bfloat16*)&lo)[3] = lw;
    *(uint2*)(row + c4)        = hi;
    *(uint2*)(row + 512 + c4)  = lo;
    *(uint2*)(row + 1024 + c4) = hi;
}

// ---------------------------------------------------------------------------
// Kernel 3b: Bop[n][k] = (k<1024 ? Mh : Ml)[k%512][n]   (bf16, [512, 1536])
// ---------------------------------------------------------------------------
__global__ void split_B_kernel() {
    const int t = blockIdx.x * blockDim.x + threadIdx.x;  // 196,608 threads
    const int n = t / 384;
    const int k4 = (t % 384) * 4;
    const int region = k4 >> 9;       // 0,1 -> hi ; 2 -> lo
    const int kk = k4 & 511;
    __nv_bfloat16 o[4];
#pragma unroll
    for (int j = 0; j < 4; j++) {
        float v = g_M[(kk + j) * D_SZ + n];
        __nv_bfloat16 h = __float2bfloat16_rn(v);
        o[j] = (region < 2) ? h : __float2bfloat16_rn(v - __bfloat162float(h));
    }
    *(uint2*)(g_Bop + (size_t)n * KC + k4) = *(uint2*)o;
}

// ---------------------------------------------------------------------------
// Kernel 4: warp-MMA bf16 GEMM: q2[8192,512] = A'[8192,1536] @ Bop^T + c
// CTA 128x128, 8 warps (32x64 warp tile), k-step 32, cp.async double buffer.
// ---------------------------------------------------------------------------
__global__ void __launch_bounds__(256, 2)
gemm_mma_kernel() {
    __shared__ __align__(16) __nv_bfloat16 sA[2][128 * ASTRIDE];
    __shared__ __align__(16) __nv_bfloat16 sB[2][128 * ASTRIDE];

    const int tid = threadIdx.x;
    const int lane = tid & 31;
    const int wid = tid >> 5;
    const int m0 = blockIdx.y * 128;
    const int n0 = blockIdx.x * 128;
    const int mbase = (wid & 3) * 32;   // warp m offset in tile
    const int nbase = (wid >> 2) * 64;  // warp n offset in tile

    const __nv_bfloat16* Ab = g_A + (size_t)m0 * KC;
    const __nv_bfloat16* Bb = g_Bop + (size_t)n0 * KC;

    // Per-thread load mapping: 2 chunks of 16B for A + 2 for B per stage
    const int lrow0 = tid >> 2;             // 0..63
    const int lcc = (tid & 3) * 8;          // half offset 0,8,16,24

    // ldmatrix lane address offsets (in halves, relative to tile, kf added later)
    const int aRow = mbase + (lane & 15);           // + mf*16
    const int aCol = (lane >= 16) ? 8 : 0;          // + kf*16
    const int bRow = nbase + ((lane >= 16) ? 8 : 0) + (lane & 7);  // + np*16
    const int bCol = ((lane >> 3) & 1) * 8;         // + kf*16

    float acc[2][8][4];
#pragma unroll
    for (int mf = 0; mf < 2; mf++)
#pragma unroll
        for (int nf = 0; nf < 8; nf++)
#pragma unroll
            for (int r = 0; r < 4; r++) acc[mf][nf][r] = 0.f;

#define LOAD_STAGE(buf, k0)                                                        \
    do {                                                                           \
        _Pragma("unroll")                                                          \
        for (int i = 0; i < 2; i++) {                                              \
            int row = lrow0 + i * 64;                                              \
            uint32_t da = smem_u32(&sA[buf][row * ASTRIDE + lcc]);                 \
            const void* pa = Ab + (size_t)row * KC + (k0) + lcc;                   \
            asm volatile("cp.async.cg.shared.global [%0], [%1], 16;"               \
                         :: "r"(da), "l"(pa) : "memory");                          \
            uint32_t db = smem_u32(&sB[buf][row * ASTRIDE + lcc]);                 \
            const void* pb = Bb + (size_t)row * KC + (k0) + lcc;                   \
            asm volatile("cp.async.cg.shared.global [%0], [%1], 16;"               \
                         :: "r"(db), "l"(pb) : "memory");                          \
        }                                                                          \
        asm volatile("cp.async.commit_group;" ::: "memory");                       \
    } while (0)

    LOAD_STAGE(0, 0);

    const int NSTEP = KC / 32;  // 48
    for (int c = 0; c < NSTEP; ++c) {
        const int buf = c & 1;
        if (c + 1 < NSTEP) {
            LOAD_STAGE(buf ^ 1, (c + 1) * 32);
            asm volatile("cp.async.wait_group 1;" ::: "memory");
        } else {
            asm volatile("cp.async.wait_group 0;" ::: "memory");
        }
        __syncthreads();

#pragma unroll
        for (int kf = 0; kf < 2; kf++) {
            uint32_t a[2][4];
#pragma unroll
            for (int mf = 0; mf < 2; mf++) {
                uint32_t addr = smem_u32(
                    &sA[buf][(aRow + mf * 16) * ASTRIDE + kf * 16 + aCol]);
                asm volatile(
                    "ldmatrix.sync.aligned.m8n8.x4.shared.b16 {%0,%1,%2,%3}, [%4];"
                    : "=r"(a[mf][0]), "=r"(a[mf][1]), "=r"(a[mf][2]), "=r"(a[mf][3])
                    : "r"(addr));
            }
            uint32_t b[4][4];
#pragma unroll
            for (int np = 0; np < 4; np++) {
                uint32_t addr = smem_u32(
                    &sB[buf][(bRow + np * 16) * ASTRIDE + kf * 16 + bCol]);
                asm volatile(
                    "ldmatrix.sync.aligned.m8n8.x4.shared.b16 {%0,%1,%2,%3}, [%4];"
                    : "=r"(b[np][0]), "=r"(b[np][1]), "=r"(b[np][2]), "=r"(b[np][3])
                    : "r"(addr));
            }
#pragma unroll
            for (int mf = 0; mf < 2; mf++)
#pragma unroll
                for (int nf = 0; nf < 8; nf++) {
                    asm volatile(
                        "mma.sync.aligned.m16n8k16.row.col.f32.bf16.bf16.f32 "
                        "{%0,%1,%2,%3}, {%4,%5,%6,%7}, {%8,%9}, {%0,%1,%2,%3};"
                        : "+f"(acc[mf][nf][0]), "+f"(acc[mf][nf][1]),
                          "+f"(acc[mf][nf][2]), "+f"(acc[mf][nf][3])
                        : "r"(a[mf][0]), "r"(a[mf][1]), "r"(a[mf][2]), "r"(a[mf][3]),
                          "r"(b[nf >> 1][(nf & 1) * 2]), "r"(b[nf >> 1][(nf & 1) * 2 + 1]));
                }
        }
        __syncthreads();
    }

    // Epilogue: acc + bias -> g_q2
    const int g = lane >> 2;
    const int t4 = lane & 3;
    float* q2p = (float*)g_q2;
#pragma unroll
    for (int mf = 0; mf < 2; mf++) {
#pragma unroll
        for (int nf = 0; nf < 8; nf++) {
            const int col = n0 + nbase + nf * 8 + t4 * 2;
            const float c0 = g_c[col], c1 = g_c[col + 1];
            const int r0 = m0 + mbase + mf * 16 + g;
            float2 v0 = make_float2(acc[mf][nf][0] + c0, acc[mf][nf][1] + c1);
            float2 v1 = make_float2(acc[mf][nf][2] + c0, acc[mf][nf][3] + c1);
            *(float2*)(q2p + (size_t)r0 * D_SZ + col) = v0;
            *(float2*)(q2p + (size_t)(r0 + 8) * D_SZ + col) = v1;
        }
    }
}

// ---------------------------------------------------------------------------
// Kernel 5: attention (unchanged — at 88.7% DRAM roofline)
// ---------------------------------------------------------------------------
__global__ void __launch_bounds__(256)
attn_kernel(const float* __restrict__ x,
            const float* __restrict__ keys,
            const float* __restrict__ values,
            float* __restrict__ out) {
    const int b = blockIdx.x;
    const int tid = threadIdx.x;
    const int lane = tid & 31;
    const int warp = tid >> 5;

    __shared__ float4 q2s[128];
    __shared__ float sc[32];
    __shared__ float attn_s[32];

    if (tid < 128) q2s[tid] = g_q2[b * 128 + tid];
    __syncthreads();

    const float4* K4 = (const float4*)keys;
#pragma unroll
    for (int kk = 0; kk < 4; kk++) {
        const int k = warp * 4 + kk;
        const long base = ((long)b * K_SZ + k) * 128;
        float s = 0.f;
#pragma unroll
        for (int i = 0; i < 4; i++) {
            float4 kv = K4[base + i * 32 + lane];
            float4 qv = q2s[i * 32 + lane];
            s = fmaf(kv.x, qv.x, s);
            s = fmaf(kv.y, qv.y, s);
            s = fmaf(kv.z, qv.z, s);
            s = fmaf(kv.w, qv.w, s);
        }
#pragma unroll
        for (int off = 16; off; off >>= 1)
            s += __shfl_xor_sync(0xffffffffu, s, off);
        if (lane == 0) sc[k] = s * 0.044194173824159216f;  // 1/sqrt(512)
    }
    __syncthreads();

    if (tid < 32) {
        float s = sc[tid];
        float m = s;
#pragma unroll
        for (int off = 16; off; off >>= 1)
            m = fmaxf(m, __shfl_xor_sync(0xffffffffu, m, off));
        float p = __expf(s - m);
        float sum = p;
#pragma unroll
        for (int off = 16; off; off >>= 1)
            sum += __shfl_xor_sync(0xffffffffu, sum, off);
        attn_s[tid] = p / sum;
    }
    __syncthreads();

    const float2* V2 = (const float2*)values;
    const float2* X2 = (const float2*)x;
    float2 acc = make_float2(0.f, 0.f);
    const long vbase = (long)b * K_SZ * 256;
#pragma unroll
    for (int k = 0; k < K_SZ; k++) {
        const float a = attn_s[k];
        float2 v = V2[vbase + k * 256 + tid];
        acc.x = fmaf(a, v.x, acc.x);
        acc.y = fmaf(a, v.y, acc.y);
    }
    float2 xv = X2[(long)b * 256 + tid];
    float2 o;
    o.x = 0.5f * xv.x + 0.5f * acc.x;
    o.y = 0.5f * xv.y + 0.5f * acc.y;
    ((float2*)out)[(long)b * 256 + tid] = o;
}

// ---------------------------------------------------------------------------
extern "C" void kernel_launch(void* const* d_in, const int* in_sizes, int n_in,
                              void* d_out, int out_size) {
    (void)in_sizes; (void)n_in; (void)out_size;
    const float* x      = (const float*)d_in[0];
    const float* keys   = (const float*)d_in[1];
    const float* values = (const float*)d_in[2];
    const float* w1     = (const float*)d_in[3];
    const float* b1     = (const float*)d_in[4];
    const float* w2     = (const float*)d_in[5];
    // d_in[6] = b2: per-row constant in scores -> cancels in softmax.
    float* out = (float*)d_out;

    compute_M_kernel<<<dim3(8, 8), 256>>>(w1, w2);
    compute_c_kernel<<<4, 128>>>(b1, w2);
    split_x_kernel<<<4096, 256>>>(x);
    split_B_kernel<<<768, 256>>>();
    gemm_mma_kernel<<<dim3(4, 64), 256>>>();
    attn_kernel<<<B_SZ, 256>>>(x, keys, values, out);
}

// round 5
// speedup vs baseline: 1.2729x; 1.0791x over previous
#include <cuda_runtime.h>
#include <cuda_bf16.h>
#include <cstdint>

// Problem constants
#define B_SZ 8192
#define K_SZ 32
#define D_SZ 512
#define KA   1024            // A cols: [xh | xl] ; Bop rows-major K: [Mh ; Ml]
#define ASTRIDE 40           // smem row stride in bf16 halves (conflict-free ldmatrix)
#define SA_HALVES (128 * ASTRIDE)

// Scratch (device globals — no allocation allowed)
__device__ float4 g_q2[B_SZ * (D_SZ / 4)];            // 16 MB: q2 = x@M + c
__device__ float  g_c[D_SZ];                          // c = b1 @ w2
__device__ __nv_bfloat16 g_A2[B_SZ * KA];             // 16 MB: [xh | xl]
__device__ __nv_bfloat16 g_Bop[D_SZ * KA];            // 1 MB:  Bop[n][k] = [Mh;Ml] K-major

__device__ __forceinline__ uint32_t smem_u32(const void* p) {
    uint32_t a;
    asm("{ .reg .u64 t; cvta.to.shared.u64 t, %1; cvt.u32.u64 %0, t; }" : "=r"(a) : "l"(p));
    return a;
}

// ---------------------------------------------------------------------------
// Kernel 1: M[d,j] = sum_e w1[e,d]*w2[e,j]; epilogue writes Bop hi/lo directly.
// ---------------------------------------------------------------------------
__global__ void compute_M_kernel(const float* __restrict__ w1,
                                 const float* __restrict__ w2) {
    __shared__ float As[16][64];
    __shared__ float Bs[16][64];
    const int tid = threadIdx.x;
    const int lRow = tid / 16;
    const int lCol = (tid % 16) * 4;
    const int d0 = blockIdx.y * 64;
    const int j0 = blockIdx.x * 64;
    const int tRow = (tid / 16) * 4;
    const int tCol = (tid % 16) * 4;

    float acc[4][4] = {};
    for (int e0 = 0; e0 < D_SZ; e0 += 16) {
        *(float4*)&As[lRow][lCol] = *(const float4*)(w1 + (e0 + lRow) * D_SZ + d0 + lCol);
        *(float4*)&Bs[lRow][lCol] = *(const float4*)(w2 + (e0 + lRow) * D_SZ + j0 + lCol);
        __syncthreads();
#pragma unroll
        for (int e = 0; e < 16; e++) {
            float rm[4], rn[4];
#pragma unroll
            for (int i = 0; i < 4; i++) rm[i] = As[e][tRow + i];
#pragma unroll
            for (int j = 0; j < 4; j++) rn[j] = Bs[e][tCol + j];
#pragma unroll
            for (int i = 0; i < 4; i++)
#pragma unroll
                for (int j = 0; j < 4; j++)
                    acc[i][j] = fmaf(rm[i], rn[j], acc[i][j]);
        }
        __syncthreads();
    }
    // acc[i][j] = M[d0+tRow+i][j0+tCol+j].  Bop[n][k]=Mh, Bop[n][512+k]=Ml
#pragma unroll
    for (int jj = 0; jj < 4; jj++) {
        const int n = j0 + tCol + jj;
        __nv_bfloat16 h4[4], l4[4];
#pragma unroll
        for (int ii = 0; ii < 4; ii++) {
            float v = acc[ii][jj];
            __nv_bfloat16 h = __float2bfloat16_rn(v);
            h4[ii] = h;
            l4[ii] = __float2bfloat16_rn(v - __bfloat162float(h));
        }
        *(uint2*)(g_Bop + (size_t)n * KA + d0 + tRow) = *(uint2*)h4;
        *(uint2*)(g_Bop + (size_t)n * KA + 512 + d0 + tRow) = *(uint2*)l4;
    }
}

// ---------------------------------------------------------------------------
// Kernel 2: c[j] = sum_e b1[e]*w2[e,j] — 8 CTAs, e-split 4-way + smem reduce
// ---------------------------------------------------------------------------
__global__ void compute_c_kernel(const float* __restrict__ b1,
                                 const float* __restrict__ w2) {
    __shared__ float red[256];
    const int tid = threadIdx.x;
    const int j = blockIdx.x * 64 + (tid & 63);
    const int eg = tid >> 6;  // 0..3
    float s = 0.f;
    for (int e = eg * 128; e < eg * 128 + 128; e++)
        s = fmaf(b1[e], w2[e * D_SZ + j], s);
    red[tid] = s;
    __syncthreads();
    if (eg == 0)
        g_c[j] = red[tid] + red[tid + 64] + red[tid + 128] + red[tid + 192];
}

// ---------------------------------------------------------------------------
// Kernel 3: split x -> A2 = [xh | xl]  (bf16, [B, 1024])
// ---------------------------------------------------------------------------
__global__ void split_x_kernel(const float* __restrict__ x) {
    const int t = blockIdx.x * blockDim.x + threadIdx.x;  // 1,048,576 threads
    const int b = t >> 7;
    const int c4 = (t & 127) * 4;
    float4 v = *(const float4*)(x + (size_t)b * D_SZ + c4);
    __nv_bfloat16 hx = __float2bfloat16_rn(v.x), hy = __float2bfloat16_rn(v.y);
    __nv_bfloat16 hz = __float2bfloat16_rn(v.z), hw = __float2bfloat16_rn(v.w);
    __nv_bfloat16 lx = __float2bfloat16_rn(v.x - __bfloat162float(hx));
    __nv_bfloat16 ly = __float2bfloat16_rn(v.y - __bfloat162float(hy));
    __nv_bfloat16 lz = __float2bfloat16_rn(v.z - __bfloat162float(hz));
    __nv_bfloat16 lw = __float2bfloat16_rn(v.w - __bfloat162float(hw));
    __nv_bfloat16* row = g_A2 + (size_t)b * KA;
    uint2 hi, lo;
    ((__nv_bfloat16*)&hi)[0] = hx; ((__nv_bfloat16*)&hi)[1] = hy;
    ((__nv_bfloat16*)&hi)[2] = hz; ((__nv_bfloat16*)&hi)[3] = hw;
    ((__nv_bfloat16*)&lo)[0] = lx; ((__nv_bfloat16*)&lo)[1] = ly;
    ((__nv_bfloat16*)&lo)[2] = lz; ((__nv_bfloat16*)&lo)[3] = lw;
    *(uint2*)(row + c4)       = hi;
    *(uint2*)(row + 512 + c4) = lo;
}

// ---------------------------------------------------------------------------
// Kernel 4: warp-MMA bf16 GEMM: q2 = xh@Mh + xh@Ml + xl@Mh + c
// CTA 128x128, 8 warps, 32 k-steps of 32; steps 0-15 dual-B (Bh+Bl).
// Dynamic smem: sA[2] | sBh[2] | sBl[2], each 128*ASTRIDE halves.
// ---------------------------------------------------------------------------
__global__ void __launch_bounds__(256, 2)
gemm_mma_kernel() {
    extern __shared__ __nv_bfloat16 ds[];
    __nv_bfloat16* sA  = ds;
    __nv_bfloat16* sBh = ds + 2 * SA_HALVES;
    __nv_bfloat16* sBl = ds + 4 * SA_HALVES;

    const int tid = threadIdx.x;
    const int lane = tid & 31;
    const int wid = tid >> 5;
    const int m0 = blockIdx.y * 128;
    const int n0 = blockIdx.x * 128;
    const int mbase = (wid & 3) * 32;
    const int nbase = (wid >> 2) * 64;

    const __nv_bfloat16* Ab = g_A2 + (size_t)m0 * KA;
    const __nv_bfloat16* Bb = g_Bop + (size_t)n0 * KA;

    const int lrow0 = tid >> 2;         // 0..63
    const int lcc = (tid & 3) * 8;      // 0,8,16,24 halves

    const int aRow = mbase + (lane & 15);
    const int aCol = (lane >= 16) ? 8 : 0;
    const int bRow = nbase + ((lane >= 16) ? 8 : 0) + (lane & 7);
    const int bCol = ((lane >> 3) & 1) * 8;

    float acc[2][8][4];
#pragma unroll
    for (int mf = 0; mf < 2; mf++)
#pragma unroll
        for (int nf = 0; nf < 8; nf++)
#pragma unroll
            for (int r = 0; r < 4; r++) acc[mf][nf][r] = 0.f;

#define LOAD_STAGE(buf, c)                                                          \
    do {                                                                            \
        const int kb = ((c) & 15) * 32;                                             \
        _Pragma("unroll")                                                           \
        for (int i = 0; i < 2; i++) {                                               \
            int row = lrow0 + i * 64;                                               \
            uint32_t da = smem_u32(&sA[(buf) * SA_HALVES + row * ASTRIDE + lcc]);   \
            const void* pa = Ab + (size_t)row * KA + (c) * 32 + lcc;                \
            asm volatile("cp.async.cg.shared.global [%0], [%1], 16;"                \
                         :: "r"(da), "l"(pa) : "memory");                           \
            uint32_t dh = smem_u32(&sBh[(buf) * SA_HALVES + row * ASTRIDE + lcc]);  \
            const void* ph = Bb + (size_t)row * KA + kb + lcc;                      \
            asm volatile("cp.async.cg.shared.global [%0], [%1], 16;"                \
                         :: "r"(dh), "l"(ph) : "memory");                           \
            if ((c) < 16) {                                                         \
                uint32_t dl = smem_u32(&sBl[(buf) * SA_HALVES + row * ASTRIDE + lcc]); \
                const void* pl = Bb + (size_t)row * KA + 512 + kb + lcc;            \
                asm volatile("cp.async.cg.shared.global [%0], [%1], 16;"            \
                             :: "r"(dl), "l"(pl) : "memory");                       \
            }                                                                       \
        }                                                                           \
        asm volatile("cp.async.commit_group;" ::: "memory");                        \
    } while (0)

    LOAD_STAGE(0, 0);

    const int NSTEP = 32;
    for (int c = 0; c < NSTEP; ++c) {
        const int buf = c & 1;
        if (c + 1 < NSTEP) {
            LOAD_STAGE(buf ^ 1, c + 1);
            asm volatile("cp.async.wait_group 1;" ::: "memory");
        } else {
            asm volatile("cp.async.wait_group 0;" ::: "memory");
        }
        __syncthreads();

#pragma unroll
        for (int kf = 0; kf < 2; kf++) {
            uint32_t a[2][4];
#pragma unroll
            for (int mf = 0; mf < 2; mf++) {
                uint32_t addr = smem_u32(
                    &sA[buf * SA_HALVES + (aRow + mf * 16) * ASTRIDE + kf * 16 + aCol]);
                asm volatile(
                    "ldmatrix.sync.aligned.m8n8.x4.shared.b16 {%0,%1,%2,%3}, [%4];"
                    : "=r"(a[mf][0]), "=r"(a[mf][1]), "=r"(a[mf][2]), "=r"(a[mf][3])
                    : "r"(addr));
            }
            uint32_t b[4][4];
#pragma unroll
            for (int np = 0; np < 4; np++) {
                uint32_t addr = smem_u32(
                    &sBh[buf * SA_HALVES + (bRow + np * 16) * ASTRIDE + kf * 16 + bCol]);
                asm volatile(
                    "ldmatrix.sync.aligned.m8n8.x4.shared.b16 {%0,%1,%2,%3}, [%4];"
                    : "=r"(b[np][0]), "=r"(b[np][1]), "=r"(b[np][2]), "=r"(b[np][3])
                    : "r"(addr));
            }
#pragma unroll
            for (int mf = 0; mf < 2; mf++)
#pragma unroll
                for (int nf = 0; nf < 8; nf++) {
                    asm volatile(
                        "mma.sync.aligned.m16n8k16.row.col.f32.bf16.bf16.f32 "
                        "{%0,%1,%2,%3}, {%4,%5,%6,%7}, {%8,%9}, {%0,%1,%2,%3};"
                        : "+f"(acc[mf][nf][0]), "+f"(acc[mf][nf][1]),
                          "+f"(acc[mf][nf][2]), "+f"(acc[mf][nf][3])
                        : "r"(a[mf][0]), "r"(a[mf][1]), "r"(a[mf][2]), "r"(a[mf][3]),
                          "r"(b[nf >> 1][(nf & 1) * 2]), "r"(b[nf >> 1][(nf & 1) * 2 + 1]));
                }
            if (c < 16) {  // xh also multiplies Ml
#pragma unroll
                for (int np = 0; np < 4; np++) {
                    uint32_t addr = smem_u32(
                        &sBl[buf * SA_HALVES + (bRow + np * 16) * ASTRIDE + kf * 16 + bCol]);
                    asm volatile(
                        "ldmatrix.sync.aligned.m8n8.x4.shared.b16 {%0,%1,%2,%3}, [%4];"
                        : "=r"(b[np][0]), "=r"(b[np][1]), "=r"(b[np][2]), "=r"(b[np][3])
                        : "r"(addr));
                }
#pragma unroll
                for (int mf = 0; mf < 2; mf++)
#pragma unroll
                    for (int nf = 0; nf < 8; nf++) {
                        asm volatile(
                            "mma.sync.aligned.m16n8k16.row.col.f32.bf16.bf16.f32 "
                            "{%0,%1,%2,%3}, {%4,%5,%6,%7}, {%8,%9}, {%0,%1,%2,%3};"
                            : "+f"(acc[mf][nf][0]), "+f"(acc[mf][nf][1]),
                              "+f"(acc[mf][nf][2]), "+f"(acc[mf][nf][3])
                            : "r"(a[mf][0]), "r"(a[mf][1]), "r"(a[mf][2]), "r"(a[mf][3]),
                              "r"(b[nf >> 1][(nf & 1) * 2]), "r"(b[nf >> 1][(nf & 1) * 2 + 1]));
                    }
            }
        }
        __syncthreads();
    }

    // Epilogue: acc + bias -> g_q2
    const int g = lane >> 2;
    const int t4 = lane & 3;
    float* q2p = (float*)g_q2;
#pragma unroll
    for (int mf = 0; mf < 2; mf++) {
#pragma unroll
        for (int nf = 0; nf < 8; nf++) {
            const int col = n0 + nbase + nf * 8 + t4 * 2;
            const float c0 = g_c[col], c1 = g_c[col + 1];
            const int r0 = m0 + mbase + mf * 16 + g;
            float2 v0 = make_float2(acc[mf][nf][0] + c0, acc[mf][nf][1] + c1);
            float2 v1 = make_float2(acc[mf][nf][2] + c0, acc[mf][nf][3] + c1);
            *(float2*)(q2p + (size_t)r0 * D_SZ + col) = v0;
            *(float2*)(q2p + (size_t)(r0 + 8) * D_SZ + col) = v1;
        }
    }
}

// ---------------------------------------------------------------------------
// Kernel 5: attention (unchanged — at 88.7% DRAM roofline)
// ---------------------------------------------------------------------------
__global__ void __launch_bounds__(256)
attn_kernel(const float* __restrict__ x,
            const float* __restrict__ keys,
            const float* __restrict__ values,
            float* __restrict__ out) {
    const int b = blockIdx.x;
    const int tid = threadIdx.x;
    const int lane = tid & 31;
    const int warp = tid >> 5;

    __shared__ float4 q2s[128];
    __shared__ float sc[32];
    __shared__ float attn_s[32];

    if (tid < 128) q2s[tid] = g_q2[b * 128 + tid];
    __syncthreads();

    const float4* K4 = (const float4*)keys;
#pragma unroll
    for (int kk = 0; kk < 4; kk++) {
        const int k = warp * 4 + kk;
        const long base = ((long)b * K_SZ + k) * 128;
        float s = 0.f;
#pragma unroll
        for (int i = 0; i < 4; i++) {
            float4 kv = K4[base + i * 32 + lane];
            float4 qv = q2s[i * 32 + lane];
            s = fmaf(kv.x, qv.x, s);
            s = fmaf(kv.y, qv.y, s);
            s = fmaf(kv.z, qv.z, s);
            s = fmaf(kv.w, qv.w, s);
        }
#pragma unroll
        for (int off = 16; off; off >>= 1)
            s += __shfl_xor_sync(0xffffffffu, s, off);
        if (lane == 0) sc[k] = s * 0.044194173824159216f;  // 1/sqrt(512)
    }
    __syncthreads();

    if (tid < 32) {
        float s = sc[tid];
        float m = s;
#pragma unroll
        for (int off = 16; off; off >>= 1)
            m = fmaxf(m, __shfl_xor_sync(0xffffffffu, m, off));
        float p = __expf(s - m);
        float sum = p;
#pragma unroll
        for (int off = 16; off; off >>= 1)
            sum += __shfl_xor_sync(0xffffffffu, sum, off);
        attn_s[tid] = p / sum;
    }
    __syncthreads();

    const float2* V2 = (const float2*)values;
    const float2* X2 = (const float2*)x;
    float2 acc = make_float2(0.f, 0.f);
    const long vbase = (long)b * K_SZ * 256;
#pragma unroll
    for (int k = 0; k < K_SZ; k++) {
        const float a = attn_s[k];
        float2 v = V2[vbase + k * 256 + tid];
        acc.x = fmaf(a, v.x, acc.x);
        acc.y = fmaf(a, v.y, acc.y);
    }
    float2 xv = X2[(long)b * 256 + tid];
    float2 o;
    o.x = 0.5f * xv.x + 0.5f * acc.x;
    o.y = 0.5f * xv.y + 0.5f * acc.y;
    ((float2*)out)[(long)b * 256 + tid] = o;
}

// ---------------------------------------------------------------------------
extern "C" void kernel_launch(void* const* d_in, const int* in_sizes, int n_in,
                              void* d_out, int out_size) {
    (void)in_sizes; (void)n_in; (void)out_size;
    const float* x      = (const float*)d_in[0];
    const float* keys   = (const float*)d_in[1];
    const float* values = (const float*)d_in[2];
    const float* w1     = (const float*)d_in[3];
    const float* b1     = (const float*)d_in[4];
    const float* w2     = (const float*)d_in[5];
    // d_in[6] = b2: per-row constant in scores -> cancels in softmax.
    float* out = (float*)d_out;

    const int gemm_smem = 6 * SA_HALVES * (int)sizeof(__nv_bfloat16);  // 61440
    cudaFuncSetAttribute(gemm_mma_kernel,
                         cudaFuncAttributeMaxDynamicSharedMemorySize, gemm_smem);

    compute_M_kernel<<<dim3(8, 8), 256>>>(w1, w2);   // writes g_Bop (bf16 hi/lo)
    compute_c_kernel<<<8, 256>>>(b1, w2);
    split_x_kernel<<<4096, 256>>>(x);                // writes g_A2 [xh|xl]
    gemm_mma_kernel<<<dim3(4, 64), 256, gemm_smem>>>();
    attn_kernel<<<B_SZ, 256>>>(x, keys, values, out);
}

// round 6
// speedup vs baseline: 1.3892x; 1.0913x over previous
#include <cuda_runtime.h>
#include <cuda_bf16.h>
#include <cstdint>

// Problem constants
#define B_SZ 8192
#define K_SZ 32
#define D_SZ 512
#define KA   1024            // A cols: [xh | xl] ; Bop K-range: [Mh ; Ml]
#define ASTRIDE 40           // smem row stride in bf16 halves (conflict-free ldmatrix)
#define SA_HALVES (128 * ASTRIDE)
#define NPART 8              // split-K factor for compute_M

// Scratch (device globals — no allocation allowed)
__device__ float4 g_q2[B_SZ * (D_SZ / 4)];            // 16 MB: q2 = x@M + c
__device__ float  g_c[D_SZ];                          // c = b1 @ w2
__device__ __nv_bfloat16 g_A2[B_SZ * KA];             // 16 MB: [xh | xl]
__device__ __nv_bfloat16 g_Bop[D_SZ * KA];            // 1 MB:  Bop[n][k] = [Mh;Ml] K-major
__device__ float g_MpartT[NPART][D_SZ * D_SZ];        // 8 MB:  partial M, transposed [n*512+d]

__device__ __forceinline__ uint32_t smem_u32(const void* p) {
    uint32_t a;
    asm("{ .reg .u64 t; cvta.to.shared.u64 t, %1; cvt.u32.u64 %0, t; }" : "=r"(a) : "l"(p));
    return a;
}

// ---------------------------------------------------------------------------
// Kernel 1a: split-K partial of M: part[z][n][d] = sum_{e in slice z} w1[e,d]w2[e,n]
// grid (8,8,8) = (j-block, d-block, k-slice), 256 threads, 64x64 tile, 4 iters.
// ---------------------------------------------------------------------------
__global__ void compute_M_part_kernel(const float* __restrict__ w1,
                                      const float* __restrict__ w2) {
    __shared__ float As[16][64];
    __shared__ float Bs[16][64];
    const int tid = threadIdx.x;
    const int lRow = tid / 16;
    const int lCol = (tid % 16) * 4;
    const int d0 = blockIdx.y * 64;
    const int j0 = blockIdx.x * 64;
    const int e_lo = blockIdx.z * 64;
    const int tRow = (tid / 16) * 4;
    const int tCol = (tid % 16) * 4;

    float acc[4][4] = {};
    for (int e0 = e_lo; e0 < e_lo + 64; e0 += 16) {
        *(float4*)&As[lRow][lCol] = *(const float4*)(w1 + (e0 + lRow) * D_SZ + d0 + lCol);
        *(float4*)&Bs[lRow][lCol] = *(const float4*)(w2 + (e0 + lRow) * D_SZ + j0 + lCol);
        __syncthreads();
#pragma unroll
        for (int e = 0; e < 16; e++) {
            float rm[4], rn[4];
#pragma unroll
            for (int i = 0; i < 4; i++) rm[i] = As[e][tRow + i];
#pragma unroll
            for (int j = 0; j < 4; j++) rn[j] = Bs[e][tCol + j];
#pragma unroll
            for (int i = 0; i < 4; i++)
#pragma unroll
                for (int j = 0; j < 4; j++)
                    acc[i][j] = fmaf(rm[i], rn[j], acc[i][j]);
        }
        __syncthreads();
    }
    // transposed partial: [n][d]
    float* part = g_MpartT[blockIdx.z];
#pragma unroll
    for (int jj = 0; jj < 4; jj++) {
        const int n = j0 + tCol + jj;
        float4 v = make_float4(acc[0][jj], acc[1][jj], acc[2][jj], acc[3][jj]);
        *(float4*)(part + (size_t)n * D_SZ + d0 + tRow) = v;
    }
}

// ---------------------------------------------------------------------------
// Kernel 1b: reduce partials, split hi/lo, write g_Bop.
// grid 256 x 256 threads; thread -> (n, d0..d0+3)
// ---------------------------------------------------------------------------
__global__ void reduce_split_kernel() {
    const int idx = blockIdx.x * blockDim.x + threadIdx.x;  // 65536
    const int n = idx >> 7;
    const int d0 = (idx & 127) * 4;
    float4 s = make_float4(0.f, 0.f, 0.f, 0.f);
#pragma unroll
    for (int p = 0; p < NPART; p++) {
        float4 v = *(const float4*)(g_MpartT[p] + (size_t)n * D_SZ + d0);
        s.x += v.x; s.y += v.y; s.z += v.z; s.w += v.w;
    }
    __nv_bfloat16 h4[4], l4[4];
    const float sv[4] = {s.x, s.y, s.z, s.w};
#pragma unroll
    for (int i = 0; i < 4; i++) {
        __nv_bfloat16 h = __float2bfloat16_rn(sv[i]);
        h4[i] = h;
        l4[i] = __float2bfloat16_rn(sv[i] - __bfloat162float(h));
    }
    *(uint2*)(g_Bop + (size_t)n * KA + d0) = *(uint2*)h4;
    *(uint2*)(g_Bop + (size_t)n * KA + 512 + d0) = *(uint2*)l4;
}

// ---------------------------------------------------------------------------
// Kernel 2: c[j] = sum_e b1[e]*w2[e,j] — 8 CTAs, e-split 4-way + smem reduce
// ---------------------------------------------------------------------------
__global__ void compute_c_kernel(const float* __restrict__ b1,
                                 const float* __restrict__ w2) {
    __shared__ float red[256];
    const int tid = threadIdx.x;
    const int j = blockIdx.x * 64 + (tid & 63);
    const int eg = tid >> 6;  // 0..3
    float s = 0.f;
    for (int e = eg * 128; e < eg * 128 + 128; e++)
        s = fmaf(b1[e], w2[e * D_SZ + j], s);
    red[tid] = s;
    __syncthreads();
    if (eg == 0)
        g_c[j] = red[tid] + red[tid + 64] + red[tid + 128] + red[tid + 192];
}

// ---------------------------------------------------------------------------
// Kernel 3: split x -> A2 = [xh | xl]  (bf16, [B, 1024])
// ---------------------------------------------------------------------------
__global__ void split_x_kernel(const float* __restrict__ x) {
    const int t = blockIdx.x * blockDim.x + threadIdx.x;  // 1,048,576 threads
    const int b = t >> 7;
    const int c4 = (t & 127) * 4;
    float4 v = *(const float4*)(x + (size_t)b * D_SZ + c4);
    __nv_bfloat16 hx = __float2bfloat16_rn(v.x), hy = __float2bfloat16_rn(v.y);
    __nv_bfloat16 hz = __float2bfloat16_rn(v.z), hw = __float2bfloat16_rn(v.w);
    __nv_bfloat16 lx = __float2bfloat16_rn(v.x - __bfloat162float(hx));
    __nv_bfloat16 ly = __float2bfloat16_rn(v.y - __bfloat162float(hy));
    __nv_bfloat16 lz = __float2bfloat16_rn(v.z - __bfloat162float(hz));
    __nv_bfloat16 lw = __float2bfloat16_rn(v.w - __bfloat162float(hw));
    __nv_bfloat16* row = g_A2 + (size_t)b * KA;
    uint2 hi, lo;
    ((__nv_bfloat16*)&hi)[0] = hx; ((__nv_bfloat16*)&hi)[1] = hy;
    ((__nv_bfloat16*)&hi)[2] = hz; ((__nv_bfloat16*)&hi)[3] = hw;
    ((__nv_bfloat16*)&lo)[0] = lx; ((__nv_bfloat16*)&lo)[1] = ly;
    ((__nv_bfloat16*)&lo)[2] = lz; ((__nv_bfloat16*)&lo)[3] = lw;
    *(uint2*)(row + c4)       = hi;
    *(uint2*)(row + 512 + c4) = lo;
}

// ---------------------------------------------------------------------------
// Kernel 4: warp-MMA bf16 GEMM: q2 = xh@Mh + xh@Ml + xl@Mh + c
// CTA 128x128, 8 warps, 32 k-steps; steps 0-15 dual-B. 3-stage cp.async.
// Dynamic smem: sA[3] | sBh[3] | sBl[3], each 128*ASTRIDE halves (92,160 B).
// ---------------------------------------------------------------------------
__global__ void __launch_bounds__(256, 2)
gemm_mma_kernel() {
    extern __shared__ __nv_bfloat16 ds[];
    __nv_bfloat16* sA  = ds;
    __nv_bfloat16* sBh = ds + 3 * SA_HALVES;
    __nv_bfloat16* sBl = ds + 6 * SA_HALVES;

    const int tid = threadIdx.x;
    const int lane = tid & 31;
    const int wid = tid >> 5;
    const int m0 = blockIdx.y * 128;
    const int n0 = blockIdx.x * 128;
    const int mbase = (wid & 3) * 32;
    const int nbase = (wid >> 2) * 64;

    const __nv_bfloat16* Ab = g_A2 + (size_t)m0 * KA;
    const __nv_bfloat16* Bb = g_Bop + (size_t)n0 * KA;

    const int lrow0 = tid >> 2;         // 0..63
    const int lcc = (tid & 3) * 8;      // 0,8,16,24 halves

    const int aRow = mbase + (lane & 15);
    const int aCol = (lane >= 16) ? 8 : 0;
    const int bRow = nbase + ((lane >= 16) ? 8 : 0) + (lane & 7);
    const int bCol = ((lane >> 3) & 1) * 8;

    float acc[2][8][4];
#pragma unroll
    for (int mf = 0; mf < 2; mf++)
#pragma unroll
        for (int nf = 0; nf < 8; nf++)
#pragma unroll
            for (int r = 0; r < 4; r++) acc[mf][nf][r] = 0.f;

    const int NSTEP = 32;

    // Always commits (possibly empty) so wait_group counting stays uniform.
#define LOAD_STAGE(buf, c)                                                          \
    do {                                                                            \
        if ((c) < NSTEP) {                                                          \
            const int kb = ((c) & 15) * 32;                                         \
            _Pragma("unroll")                                                       \
            for (int i = 0; i < 2; i++) {                                           \
                int row = lrow0 + i * 64;                                           \
                uint32_t da = smem_u32(&sA[(buf) * SA_HALVES + row * ASTRIDE + lcc]); \
                const void* pa = Ab + (size_t)row * KA + (c) * 32 + lcc;            \
                asm volatile("cp.async.cg.shared.global [%0], [%1], 16;"            \
                             :: "r"(da), "l"(pa) : "memory");                       \
                uint32_t dh = smem_u32(&sBh[(buf) * SA_HALVES + row * ASTRIDE + lcc]); \
                const void* ph = Bb + (size_t)row * KA + kb + lcc;                  \
                asm volatile("cp.async.cg.shared.global [%0], [%1], 16;"            \
                             :: "r"(dh), "l"(ph) : "memory");                       \
                if ((c) < 16) {                                                     \
                    uint32_t dl = smem_u32(&sBl[(buf) * SA_HALVES + row * ASTRIDE + lcc]); \
                    const void* pl = Bb + (size_t)row * KA + 512 + kb + lcc;        \
                    asm volatile("cp.async.cg.shared.global [%0], [%1], 16;"        \
                                 :: "r"(dl), "l"(pl) : "memory");                   \
                }                                                                   \
            }                                                                       \
        }                                                                           \
        asm volatile("cp.async.commit_group;" ::: "memory");                        \
    } while (0)

    LOAD_STAGE(0, 0);
    LOAD_STAGE(1, 1);

    int buf = 0, nbuf2 = 2;  // (c+2) % 3
    for (int c = 0; c < NSTEP; ++c) {
        LOAD_STAGE(nbuf2, c + 2);
        asm volatile("cp.async.wait_group 2;" ::: "memory");
        __syncthreads();

#pragma unroll
        for (int kf = 0; kf < 2; kf++) {
            uint32_t a[2][4];
#pragma unroll
            for (int mf = 0; mf < 2; mf++) {
                uint32_t addr = smem_u32(
                    &sA[buf * SA_HALVES + (aRow + mf * 16) * ASTRIDE + kf * 16 + aCol]);
                asm volatile(
                    "ldmatrix.sync.aligned.m8n8.x4.shared.b16 {%0,%1,%2,%3}, [%4];"
                    : "=r"(a[mf][0]), "=r"(a[mf][1]), "=r"(a[mf][2]), "=r"(a[mf][3])
                    : "r"(addr));
            }
            uint32_t b[4][4];
#pragma unroll
            for (int np = 0; np < 4; np++) {
                uint32_t addr = smem_u32(
                    &sBh[buf * SA_HALVES + (bRow + np * 16) * ASTRIDE + kf * 16 + bCol]);
                asm volatile(
                    "ldmatrix.sync.aligned.m8n8.x4.shared.b16 {%0,%1,%2,%3}, [%4];"
                    : "=r"(b[np][0]), "=r"(b[np][1]), "=r"(b[np][2]), "=r"(b[np][3])
                    : "r"(addr));
            }
#pragma unroll
            for (int mf = 0; mf < 2; mf++)
#pragma unroll
                for (int nf = 0; nf < 8; nf++) {
                    asm volatile(
                        "mma.sync.aligned.m16n8k16.row.col.f32.bf16.bf16.f32 "
                        "{%0,%1,%2,%3}, {%4,%5,%6,%7}, {%8,%9}, {%0,%1,%2,%3};"
                        : "+f"(acc[mf][nf][0]), "+f"(acc[mf][nf][1]),
                          "+f"(acc[mf][nf][2]), "+f"(acc[mf][nf][3])
                        : "r"(a[mf][0]), "r"(a[mf][1]), "r"(a[mf][2]), "r"(a[mf][3]),
                          "r"(b[nf >> 1][(nf & 1) * 2]), "r"(b[nf >> 1][(nf & 1) * 2 + 1]));
                }
            if (c < 16) {  // xh also multiplies Ml
#pragma unroll
                for (int np = 0; np < 4; np++) {
                    uint32_t addr = smem_u32(
                        &sBl[buf * SA_HALVES + (bRow + np * 16) * ASTRIDE + kf * 16 + bCol]);
                    asm volatile(
                        "ldmatrix.sync.aligned.m8n8.x4.shared.b16 {%0,%1,%2,%3}, [%4];"
                        : "=r"(b[np][0]), "=r"(b[np][1]), "=r"(b[np][2]), "=r"(b[np][3])
                        : "r"(addr));
                }
#pragma unroll
                for (int mf = 0; mf < 2; mf++)
#pragma unroll
                    for (int nf = 0; nf < 8; nf++) {
                        asm volatile(
                            "mma.sync.aligned.m16n8k16.row.col.f32.bf16.bf16.f32 "
                            "{%0,%1,%2,%3}, {%4,%5,%6,%7}, {%8,%9}, {%0,%1,%2,%3};"
                            : "+f"(acc[mf][nf][0]), "+f"(acc[mf][nf][1]),
                              "+f"(acc[mf][nf][2]), "+f"(acc[mf][nf][3])
                            : "r"(a[mf][0]), "r"(a[mf][1]), "r"(a[mf][2]), "r"(a[mf][3]),
                              "r"(b[nf >> 1][(nf & 1) * 2]), "r"(b[nf >> 1][(nf & 1) * 2 + 1]));
                    }
            }
        }
        __syncthreads();
        buf = (buf == 2) ? 0 : buf + 1;
        nbuf2 = (nbuf2 == 2) ? 0 : nbuf2 + 1;
    }

    // Epilogue: acc + bias -> g_q2
    const int g = lane >> 2;
    const int t4 = lane & 3;
    float* q2p = (float*)g_q2;
#pragma unroll
    for (int mf = 0; mf < 2; mf++) {
#pragma unroll
        for (int nf = 0; nf < 8; nf++) {
            const int col = n0 + nbase + nf * 8 + t4 * 2;
            const float c0 = g_c[col], c1 = g_c[col + 1];
            const int r0 = m0 + mbase + mf * 16 + g;
            float2 v0 = make_float2(acc[mf][nf][0] + c0, acc[mf][nf][1] + c1);
            float2 v1 = make_float2(acc[mf][nf][2] + c0, acc[mf][nf][3] + c1);
            *(float2*)(q2p + (size_t)r0 * D_SZ + col) = v0;
            *(float2*)(q2p + (size_t)(r0 + 8) * D_SZ + col) = v1;
        }
    }
}

// ---------------------------------------------------------------------------
// Kernel 5: attention (unchanged — at 88.7% DRAM roofline)
// ---------------------------------------------------------------------------
__global__ void __launch_bounds__(256)
attn_kernel(const float* __restrict__ x,
            const float* __restrict__ keys,
            const float* __restrict__ values,
            float* __restrict__ out) {
    const int b = blockIdx.x;
    const int tid = threadIdx.x;
    const int lane = tid & 31;
    const int warp = tid >> 5;

    __shared__ float4 q2s[128];
    __shared__ float sc[32];
    __shared__ float attn_s[32];

    if (tid < 128) q2s[tid] = g_q2[b * 128 + tid];
    __syncthreads();

    const float4* K4 = (const float4*)keys;
#pragma unroll
    for (int kk = 0; kk < 4; kk++) {
        const int k = warp * 4 + kk;
        const long base = ((long)b * K_SZ + k) * 128;
        float s = 0.f;
#pragma unroll
        for (int i = 0; i < 4; i++) {
            float4 kv = K4[base + i * 32 + lane];
            float4 qv = q2s[i * 32 + lane];
            s = fmaf(kv.x, qv.x, s);
            s = fmaf(kv.y, qv.y, s);
            s = fmaf(kv.z, qv.z, s);
            s = fmaf(kv.w, qv.w, s);
        }
#pragma unroll
        for (int off = 16; off; off >>= 1)
            s += __shfl_xor_sync(0xffffffffu, s, off);
        if (lane == 0) sc[k] = s * 0.044194173824159216f;  // 1/sqrt(512)
    }
    __syncthreads();

    if (tid < 32) {
        float s = sc[tid];
        float m = s;
#pragma unroll
        for (int off = 16; off; off >>= 1)
            m = fmaxf(m, __shfl_xor_sync(0xffffffffu, m, off));
        float p = __expf(s - m);
        float sum = p;
#pragma unroll
        for (int off = 16; off; off >>= 1)
            sum += __shfl_xor_sync(0xffffffffu, sum, off);
        attn_s[tid] = p / sum;
    }
    __syncthreads();

    const float2* V2 = (const float2*)values;
    const float2* X2 = (const float2*)x;
    float2 acc = make_float2(0.f, 0.f);
    const long vbase = (long)b * K_SZ * 256;
#pragma unroll
    for (int k = 0; k < K_SZ; k++) {
        const float a = attn_s[k];
        float2 v = V2[vbase + k * 256 + tid];
        acc.x = fmaf(a, v.x, acc.x);
        acc.y = fmaf(a, v.y, acc.y);
    }
    float2 xv = X2[(long)b * 256 + tid];
    float2 o;
    o.x = 0.5f * xv.x + 0.5f * acc.x;
    o.y = 0.5f * xv.y + 0.5f * acc.y;
    ((float2*)out)[(long)b * 256 + tid] = o;
}

// ---------------------------------------------------------------------------
extern "C" void kernel_launch(void* const* d_in, const int* in_sizes, int n_in,
                              void* d_out, int out_size) {
    (void)in_sizes; (void)n_in; (void)out_size;
    const float* x      = (const float*)d_in[0];
    const float* keys   = (const float*)d_in[1];
    const float* values = (const float*)d_in[2];
    const float* w1     = (const float*)d_in[3];
    const float* b1     = (const float*)d_in[4];
    const float* w2     = (const float*)d_in[5];
    // d_in[6] = b2: per-row constant in scores -> cancels in softmax.
    float* out = (float*)d_out;

    const int gemm_smem = 9 * SA_HALVES * (int)sizeof(__nv_bfloat16);  // 92160
    cudaFuncSetAttribute(gemm_mma_kernel,
                         cudaFuncAttributeMaxDynamicSharedMemorySize, gemm_smem);

    compute_M_part_kernel<<<dim3(8, 8, 8), 256>>>(w1, w2);
    reduce_split_kernel<<<256, 256>>>();          // writes g_Bop (bf16 hi/lo)
    compute_c_kernel<<<8, 256>>>(b1, w2);
    split_x_kernel<<<4096, 256>>>(x);             // writes g_A2 [xh|xl]
    gemm_mma_kernel<<<dim3(4, 64), 256, gemm_smem>>>();
    attn_kernel<<<B_SZ, 256>>>(x, keys, values, out);
}